// round 3
// baseline (speedup 1.0000x reference)
#include <cuda_runtime.h>

#define BATCH  16384
#define TSTEPS 60
#define HDIM   50
#define BLOCK  512            // 16 warps; 4 threads per element
#define ELPB   128            // elements per block
#define GRID   (BATCH / ELPB)
#define KPAD   52             // padded row length (floats)

// Shared layout (floats):
//  wsh   : 4*50*52 = 10400   per-gate weight rows, padded to 52
//  bias2 : 200 float2 =  400 (wih, bih+bhh) per (gate,k)
//  wlin  : 3000
//  xs    : 128*61  = 7808
//  cs    : 128*52  = 6656
//  hn    : 128*52  = 6656
#define SMEM_FLOATS (10400 + 400 + 3000 + ELPB*61 + ELPB*KPAD + ELPB*KPAD)

typedef unsigned long long ull;

__device__ __forceinline__ float ex2f(float x) {
    float r; asm("ex2.approx.f32 %0, %1;" : "=f"(r) : "f"(x)); return r;
}
__device__ __forceinline__ float rcpf(float x) {
    float r; asm("rcp.approx.f32 %0, %1;" : "=f"(r) : "f"(x)); return r;
}
__device__ __forceinline__ void ffma2(ull& d, ull a, ull b) {
    asm("fma.rn.f32x2 %0, %1, %2, %0;" : "+l"(d) : "l"(a), "l"(b));
}
__device__ __forceinline__ void unpackf2(ull v, float& lo, float& hi) {
    asm("mov.b64 {%0, %1}, %2;" : "=f"(lo), "=f"(hi) : "l"(v));
}

__global__ void __launch_bounds__(BLOCK, 1)
lstm_gate4_kernel(const float* __restrict__ x_g,
                  const float* __restrict__ wih_g,
                  const float* __restrict__ whh_g,
                  const float* __restrict__ bih_g,
                  const float* __restrict__ bhh_g,
                  const float* __restrict__ wlin_g,
                  const float* __restrict__ blin_g,
                  float* __restrict__ out_g)
{
    extern __shared__ float smem[];
    float*  wsh   = smem;                          // 10400
    float2* bias2 = (float2*)(smem + 10400);       // 200 float2
    float*  wlin  = smem + 10800;                  // 3000
    float*  xs    = smem + 13800;                  // 128*61
    float*  cs    = xs + ELPB * 61;                // 128*52
    float*  hn    = cs + ELPB * KPAD;              // 128*52

    const int tid = threadIdx.x;

    // gate order in thread space: p0=i, p1=g, p2=f, p3=o
    // row offsets in whh/bias for those gates:
    const int grow_tbl[4] = {0, 100, 50, 150};

    // ---- stage gate weights: wsh[(p*50 + k)*52 + j] ----
    for (int idx = tid; idx < 4 * HDIM * HDIM; idx += BLOCK) {
        int p   = idx / (HDIM * HDIM);
        int rem = idx % (HDIM * HDIM);
        int k   = rem / HDIM, j = rem % HDIM;
        wsh[(p * HDIM + k) * KPAD + j] = whh_g[(grow_tbl[p] + k) * HDIM + j];
    }
    for (int idx = tid; idx < 4 * HDIM; idx += BLOCK) {      // zero pads
        wsh[idx * KPAD + 50] = 0.0f;
        wsh[idx * KPAD + 51] = 0.0f;
    }
    for (int idx = tid; idx < 4 * HDIM; idx += BLOCK) {
        int p = idx / HDIM, k = idx % HDIM;
        int g = grow_tbl[p] + k;
        bias2[idx] = make_float2(wih_g[g], bih_g[g] + bhh_g[g]);
    }
    for (int idx = tid; idx < TSTEPS * HDIM; idx += BLOCK)
        wlin[idx] = wlin_g[idx];
    {
        const float* xin = x_g + (size_t)blockIdx.x * ELPB * TSTEPS;
        for (int idx = tid; idx < ELPB * TSTEPS; idx += BLOCK) {
            int el = idx / TSTEPS, t = idx % TSTEPS;
            xs[el * 61 + t] = xin[idx];
        }
    }
    for (int idx = tid; idx < ELPB * KPAD; idx += BLOCK) {
        cs[idx] = 0.0f;
        hn[idx] = 0.0f;
    }
    __syncthreads();

    const int lane = tid & 31;
    const int p    = lane >> 3;      // gate id
    const int el   = lane & 7;
    const int wid  = tid >> 5;
    const int e    = wid * 8 + el;   // element within block

    // activation constants: sigmoid for i,f,o; tanh for g (p==1)
    const float L  = 1.4426950408889634f;
    const bool  isT = (p == 1);
    const float M0 = isT ? -2.0f * L : -L;
    const float S0 = isT ?  2.0f     :  1.0f;
    const float B0 = isT ? -1.0f     :  0.0f;

    ull hp[26];
#pragma unroll
    for (int jp = 0; jp < 26; jp++) hp[jp] = 0ull;

    float acc = 0.0f;
    const ulonglong2* myw = (const ulonglong2*)(wsh + p * HDIM * KPAD);
    const float2*     myb = bias2 + p * HDIM;
    float*            myc = cs + e * KPAD;
    float*            myh = hn + e * KPAD;
    const float*      myx = xs + e * 61;

    for (int t = 0; t < TSTEPS; t++) {
        const float xv = myx[t];
        const float* wl = wlin + t * HDIM;

#pragma unroll 2
        for (int k = 0; k < HDIM; k++) {
            const float2 bw = myb[k];
            ull pA = 0ull, pB = 0ull;
            const ulonglong2* wr = myw + k * 13;  // 13 x 16B = 52 floats
#pragma unroll
            for (int jp = 0; jp < 13; jp++) {
                const ulonglong2 w = wr[jp];      // broadcast LDS.128
                ffma2(pA, hp[2 * jp],     w.x);
                ffma2(pB, hp[2 * jp + 1], w.y);
            }
            float a0, a1, b0, b1;
            unpackf2(pA, a0, a1);
            unpackf2(pB, b0, b1);
            const float s = fmaf(xv, bw.x, bw.y) + ((a0 + a1) + (b0 + b1));

            // own gate activation
            const float act = fmaf(S0, rcpf(1.0f + ex2f(M0 * s)), B0);

            const float s1 = __shfl_xor_sync(0xffffffffu, act, 8);
            const float ig = act * s1;             // valid on p0,p1 (i*g)
            const float cold = myc[k];             // broadcast per element
            const float fc = act * cold;           // valid on p2 (f*c)
            const float sel = (p == 2) ? fc : act; // p3 contributes o
            const float s2 = __shfl_xor_sync(0xffffffffu, sel, 16);
            // p0: s2 = fc ; p1: s2 = o
            const float cn = ig + s2;              // valid on p0
            const float s3 = __shfl_xor_sync(0xffffffffu, s2, 8); // p0 <- o
            const float th = fmaf(2.0f, rcpf(1.0f + ex2f(-2.0f * L * cn)), -1.0f);
            const float hv = th * s3;              // valid on p0

            if (p == 0) {
                myc[k] = cn;
                myh[k] = hv;
                acc = fmaf(hv, wl[k], acc);
            }
        }

        __syncwarp();
#pragma unroll
        for (int jp = 0; jp < 26; jp++)
            hp[jp] = *(const ull*)(myh + 2 * jp);  // LDS.64, pad pair is 0
        __syncwarp();
    }

    if (p == 0)
        out_g[(size_t)blockIdx.x * ELPB + e] = acc + blin_g[0];
}

extern "C" void kernel_launch(void* const* d_in, const int* in_sizes, int n_in,
                              void* d_out, int out_size)
{
    const float* x    = (const float*)d_in[0];
    const float* wih  = (const float*)d_in[1];
    const float* whh  = (const float*)d_in[2];
    const float* bih  = (const float*)d_in[3];
    const float* bhh  = (const float*)d_in[4];
    const float* wlin = (const float*)d_in[5];
    const float* blin = (const float*)d_in[6];
    float* out = (float*)d_out;

    const size_t smem_bytes = (size_t)SMEM_FLOATS * sizeof(float);
    cudaFuncSetAttribute(lstm_gate4_kernel,
                         cudaFuncAttributeMaxDynamicSharedMemorySize,
                         (int)smem_bytes);
    lstm_gate4_kernel<<<GRID, BLOCK, smem_bytes>>>(x, wih, whh, bih, bhh,
                                                   wlin, blin, out);
}